// round 2
// baseline (speedup 1.0000x reference)
#include <cuda_runtime.h>
#include <cstdint>

#define N_NODES 500000

// Per-node accumulator: sum over incoming edges of (cos(dtheta), sin(dtheta)).
// 500k * 8B = 4 MB static device scratch (allocation-free rule).
__device__ float2 g_acc[N_NODES];

// ---------------------------------------------------------------------------
// Kernel 1: zero the accumulator
// ---------------------------------------------------------------------------
__global__ void zero_acc_kernel(int n) {
    int i = blockIdx.x * blockDim.x + threadIdx.x;
    if (i < n) g_acc[i] = make_float2(0.f, 0.f);
}

// ---------------------------------------------------------------------------
// Kernel 2: edge kernel.  For each edge: dtheta = theta[src]-theta[dst];
// atomically accumulate (cos, sin) into g_acc[dst].
// NOTE: src/dst are int32 (JAX without x64 downcasts the requested int64).
// Unrolled for memory-level parallelism on the random gathers.
// ---------------------------------------------------------------------------
__global__ void edge_kernel(const float* __restrict__ theta,
                            const int* __restrict__ src,
                            const int* __restrict__ dst,
                            int n_edges) {
    const int UNROLL = 8;
    long long base = (long long)blockIdx.x * blockDim.x * UNROLL + threadIdx.x;

    int   d_idx[UNROLL];
    float dth[UNROLL];
    int   cnt = 0;

    // Phase 1: batch the index loads + theta gathers (maximize MLP)
    #pragma unroll
    for (int u = 0; u < UNROLL; u++) {
        long long e = base + (long long)u * blockDim.x;
        if (e < n_edges) {
            int s = __ldg(&src[e]);
            int d = __ldg(&dst[e]);
            float ts = __ldg(&theta[s]);
            float td = __ldg(&theta[d]);
            d_idx[cnt] = d;
            dth[cnt]   = ts - td;
            cnt++;
        }
    }

    // Phase 2: sincos + vector reduction (float2 atomicAdd -> RED.v2.f32)
    #pragma unroll
    for (int u = 0; u < UNROLL; u++) {
        if (u < cnt) {
            float sn, cs;
            __sincosf(dth[u], &sn, &cs);
            atomicAdd(&g_acc[d_idx[u]], make_float2(cs, sn));
        }
    }
}

// ---------------------------------------------------------------------------
// Kernel 3: node epilogue.
//   v[i]      = v0 * (cos theta_i, sin theta_i)
//   torque[i] = w0 * normalize(mean)[1]
// normalize(mean) == normalize(sum) (positive per-node scale cancels), so the
// count segment-sum is skipped entirely. Zero-degree nodes give sum = (0,0),
// norm clamped by eps, torque = 0 — identical to the reference.
// ---------------------------------------------------------------------------
__global__ void node_kernel(const float* __restrict__ theta,
                            const float* __restrict__ v0p,
                            const float* __restrict__ w0p,
                            float* __restrict__ out,
                            int n) {
    int i = blockIdx.x * blockDim.x + threadIdx.x;
    if (i >= n) return;

    float v0 = __ldg(v0p);
    float w0 = __ldg(w0p);

    float t = theta[i];
    float sn, cs;
    sincosf(t, &sn, &cs);
    out[2 * i + 0] = v0 * cs;
    out[2 * i + 1] = v0 * sn;

    float2 a = g_acc[i];
    float nrm = sqrtf(a.x * a.x + a.y * a.y);
    float inv = a.y / fmaxf(nrm, 1e-12f);
    out[2 * n + i] = w0 * inv;
}

// ---------------------------------------------------------------------------
extern "C" void kernel_launch(void* const* d_in, const int* in_sizes, int n_in,
                              void* d_out, int out_size) {
    const float* theta = (const float*)d_in[0];
    const int*   src   = (const int*)d_in[1];
    const int*   dst   = (const int*)d_in[2];
    const float* v0p   = (const float*)d_in[3];
    const float* w0p   = (const float*)d_in[4];
    float*       out   = (float*)d_out;

    int n_nodes = in_sizes[0];   // theta has N*1 elements
    int n_edges = in_sizes[1];

    {
        int threads = 256;
        int blocks = (n_nodes + threads - 1) / threads;
        zero_acc_kernel<<<blocks, threads>>>(n_nodes);
    }
    {
        const int UNROLL = 8;
        int threads = 256;
        long long per_block = (long long)threads * UNROLL;
        int blocks = (int)((n_edges + per_block - 1) / per_block);
        edge_kernel<<<blocks, threads>>>(theta, src, dst, n_edges);
    }
    {
        int threads = 256;
        int blocks = (n_nodes + threads - 1) / threads;
        node_kernel<<<blocks, threads>>>(theta, v0p, w0p, out, n_nodes);
    }
}

// round 3
// speedup vs baseline: 1.4850x; 1.4850x over previous
#include <cuda_runtime.h>
#include <cstdint>

#define N_NODES 500000

// Static device scratch (allocation-free rule):
// g_cs[i]  = (cos theta_i, sin theta_i)   -- 4 MB gather table
// g_acc[i] = sum over incoming edges of e^{i theta_src}  -- 4 MB accumulator
__device__ float2 g_cs[N_NODES];
__device__ float2 g_acc[N_NODES];

// ---------------------------------------------------------------------------
// Kernel 1: build (cos,sin) table + zero the accumulator
// ---------------------------------------------------------------------------
__global__ void init_kernel(const float* __restrict__ theta, int n) {
    int i = blockIdx.x * blockDim.x + threadIdx.x;
    if (i < n) {
        float sn, cs;
        __sincosf(theta[i], &sn, &cs);
        g_cs[i]  = make_float2(cs, sn);
        g_acc[i] = make_float2(0.f, 0.f);
    }
}

// ---------------------------------------------------------------------------
// Kernel 2: edge kernel.
// Factorization: sum_{e->d} e^{i(ts-td)} = e^{-i td} * sum_{e->d} e^{i ts},
// so per edge we only gather e^{i theta[src]} and RED it into acc[dst].
// The e^{-i td} rotation is applied once per node in the epilogue.
// Index loads are int4-vectorized (4 edges / 16B).
// ---------------------------------------------------------------------------
__global__ void edge_kernel(const int4* __restrict__ src4,
                            const int4* __restrict__ dst4,
                            int n4,
                            const int* __restrict__ src_tail,
                            const int* __restrict__ dst_tail,
                            int n_tail) {
    const int U = 2;  // int4 groups per thread => 8 edges
    long long base = (long long)blockIdx.x * blockDim.x * U + threadIdx.x;

    int4   s[U], d[U];
    bool   ok[U];
    float2 m[U][4];

    // Phase 1: index loads (coalesced 16B)
    #pragma unroll
    for (int u = 0; u < U; u++) {
        long long g = base + (long long)u * blockDim.x;
        ok[u] = (g < n4);
        if (ok[u]) {
            s[u] = __ldg(&src4[g]);
            d[u] = __ldg(&dst4[g]);
        }
    }

    // Phase 2: batched random gathers of e^{i theta_src} (maximize MLP)
    #pragma unroll
    for (int u = 0; u < U; u++) {
        if (ok[u]) {
            m[u][0] = __ldg(&g_cs[s[u].x]);
            m[u][1] = __ldg(&g_cs[s[u].y]);
            m[u][2] = __ldg(&g_cs[s[u].z]);
            m[u][3] = __ldg(&g_cs[s[u].w]);
        }
    }

    // Phase 3: vector reductions (float2 atomicAdd -> RED .64)
    #pragma unroll
    for (int u = 0; u < U; u++) {
        if (ok[u]) {
            atomicAdd(&g_acc[d[u].x], m[u][0]);
            atomicAdd(&g_acc[d[u].y], m[u][1]);
            atomicAdd(&g_acc[d[u].z], m[u][2]);
            atomicAdd(&g_acc[d[u].w], m[u][3]);
        }
    }

    // Tail edges (n_edges % 4), handled by a few threads of block 0
    if (blockIdx.x == 0 && threadIdx.x < n_tail) {
        int sidx = __ldg(&src_tail[threadIdx.x]);
        int didx = __ldg(&dst_tail[threadIdx.x]);
        atomicAdd(&g_acc[didx], __ldg(&g_cs[sidx]));
    }
}

// ---------------------------------------------------------------------------
// Kernel 3: node epilogue.
//   v[i]      = v0 * (cos t, sin t)                (from the table)
//   S         = acc[i]  (sum of e^{i ts} over incoming edges)
//   rotated   = e^{-i t} * S  -> y = c*S.y - s*S.x
//   torque[i] = w0 * y / max(|S|, eps)             (rotation preserves norm;
//                                                   mean==sum under normalize)
// ---------------------------------------------------------------------------
__global__ void node_kernel(const float* __restrict__ v0p,
                            const float* __restrict__ w0p,
                            float* __restrict__ out,
                            int n) {
    int i = blockIdx.x * blockDim.x + threadIdx.x;
    if (i >= n) return;

    float v0 = __ldg(v0p);
    float w0 = __ldg(w0p);

    float2 cs = g_cs[i];
    out[2 * i + 0] = v0 * cs.x;
    out[2 * i + 1] = v0 * cs.y;

    float2 S = g_acc[i];
    float y   = cs.x * S.y - cs.y * S.x;
    float nrm = sqrtf(S.x * S.x + S.y * S.y);
    out[2 * n + i] = w0 * (y / fmaxf(nrm, 1e-12f));
}

// ---------------------------------------------------------------------------
extern "C" void kernel_launch(void* const* d_in, const int* in_sizes, int n_in,
                              void* d_out, int out_size) {
    const float* theta = (const float*)d_in[0];
    const int*   src   = (const int*)d_in[1];
    const int*   dst   = (const int*)d_in[2];
    const float* v0p   = (const float*)d_in[3];
    const float* w0p   = (const float*)d_in[4];
    float*       out   = (float*)d_out;

    int n_nodes = in_sizes[0];
    int n_edges = in_sizes[1];
    int n4      = n_edges / 4;
    int n_tail  = n_edges - n4 * 4;

    {
        int threads = 256;
        int blocks = (n_nodes + threads - 1) / threads;
        init_kernel<<<blocks, threads>>>(theta, n_nodes);
    }
    {
        const int U = 2;
        int threads = 256;
        long long per_block = (long long)threads * U;
        int blocks = (int)(((long long)n4 + per_block - 1) / per_block);
        if (blocks < 1) blocks = 1;
        edge_kernel<<<blocks, threads>>>((const int4*)src, (const int4*)dst, n4,
                                         src + n4 * 4, dst + n4 * 4, n_tail);
    }
    {
        int threads = 256;
        int blocks = (n_nodes + threads - 1) / threads;
        node_kernel<<<blocks, threads>>>(v0p, w0p, out, n_nodes);
    }
}